// round 3
// baseline (speedup 1.0000x reference)
#include <cuda_runtime.h>

#define NB 32
#define NCH 3
#define THREADS 128
#define B_PER_CHUNK 16
#define CHUNK_ELEMS (512*512)
#define CHUNK_F4   (CHUNK_ELEMS/4)         // 65536 float4 per (n,c) chunk
#define NCHUNKS    (16*3)                  // 48
#define NBLOCKS    (NCHUNKS * B_PER_CHUNK) // 768
#define STRIDE     (B_PER_CHUNK * THREADS) // 2048

// Global accumulators. Zero-initialized at module load; the LAST block of each
// launch resets them after reading, so every (graph-replayed) launch starts
// from zero. No separate init/final kernels.
__device__ double g_sum_d[NCH * NB];
__device__ double g_cnt [NCH * NB];
__device__ unsigned int g_ticket;

__device__ __forceinline__ void accum(float2* h, float xc, float pc, float tc, int tid)
{
    // inputs are uniform [0,1): bin is always valid; clamp only as a guard
    int b = (int)(xc * 32.0f);
    b = min(b, NB - 1);
    float2* e = &h[b * THREADS + tid];
    float2 v = *e;                 // LDS.64, conflict-free (lane stride 8B)
    v.x += pc - tc;
    v.y += 1.0f;
    *e = v;                        // STS.64
}

__global__ __launch_bounds__(THREADS, 6)
void fused_kernel(const float4* __restrict__ pred,
                  const float4* __restrict__ targ,
                  const float4* __restrict__ x,
                  float* __restrict__ out)
{
    // Per-thread privatized {sum(p-t), count} histogram: h[bin*128 + tid].
    __shared__ float2 h[NB * THREADS];
    __shared__ bool   s_last;

    const int tid = threadIdx.x;

    #pragma unroll
    for (int b = 0; b < NB; b++)
        h[b * THREADS + tid] = make_float2(0.0f, 0.0f);
    __syncthreads();

    const int chunk = blockIdx.x / B_PER_CHUNK;   // (n*3 + c)
    const int sub   = blockIdx.x % B_PER_CHUNK;
    const int chan  = chunk % NCH;
    const size_t base = (size_t)chunk * CHUNK_F4;

    int i = sub * THREADS + tid;
    #pragma unroll 2
    for (int k = 0; k < CHUNK_F4 / (2 * STRIDE); k++, i += 2 * STRIDE) {
        float4 xa = __ldcs(&x   [base + i]);
        float4 pa = __ldcs(&pred[base + i]);
        float4 ta = __ldcs(&targ[base + i]);
        float4 xb = __ldcs(&x   [base + i + STRIDE]);
        float4 pb = __ldcs(&pred[base + i + STRIDE]);
        float4 tb = __ldcs(&targ[base + i + STRIDE]);

        accum(h, xa.x, pa.x, ta.x, tid);
        accum(h, xa.y, pa.y, ta.y, tid);
        accum(h, xa.z, pa.z, ta.z, tid);
        accum(h, xa.w, pa.w, ta.w, tid);

        accum(h, xb.x, pb.x, tb.x, tid);
        accum(h, xb.y, pb.y, tb.y, tid);
        accum(h, xb.z, pb.z, tb.z, tid);
        accum(h, xb.w, pb.w, tb.w, tid);
    }
    __syncthreads();

    // Block reduce: 128 threads = 32 bins x 4 quarters of 32 entries.
    const int bin = tid >> 2;
    const int j   = tid & 3;
    const int bi  = bin * THREADS + j * 32;

    float vd = 0.0f, vc = 0.0f;
    #pragma unroll
    for (int k = 0; k < 32; k++) {
        int kk = (k + tid) & 31;
        float2 e = h[bi + kk];
        vd += e.x;
        vc += e.y;
    }

    vd += __shfl_down_sync(0xffffffffu, vd, 1);
    vc += __shfl_down_sync(0xffffffffu, vc, 1);
    vd += __shfl_down_sync(0xffffffffu, vd, 2);
    vc += __shfl_down_sync(0xffffffffu, vc, 2);

    if (j == 0) {
        int g = chan * NB + bin;
        atomicAdd(&g_sum_d[g], (double)vd);
        atomicAdd(&g_cnt [g], (double)vc);
    }

    // ---- last-block finalize (fused epilogue, no second launch) ----
    __threadfence();
    if (tid == 0) {
        unsigned int t = atomicAdd(&g_ticket, 1u);
        s_last = (t == NBLOCKS - 1);
    }
    __syncthreads();
    if (!s_last) return;

    __shared__ float buf[128];
    float d = 0.0f;
    if (tid < NCH * NB) {
        // atomic read-with-0 guarantees we see all prior atomics' results
        double cnt = atomicAdd(&g_cnt[tid], 0.0);
        double sd  = atomicAdd(&g_sum_d[tid], 0.0);
        if (cnt > 0.0) d = (float)fabs(sd / cnt);
        // reset for next launch (graph replay determinism)
        g_sum_d[tid] = 0.0;
        g_cnt [tid] = 0.0;
    }
    if (tid == 0) g_ticket = 0u;
    buf[tid] = d;
    __syncthreads();
    #pragma unroll
    for (int s = 64; s > 0; s >>= 1) {
        if (tid < s) buf[tid] += buf[tid + s];
        __syncthreads();
    }
    if (tid == 0) out[0] = buf[0] / 96.0f;
}

extern "C" void kernel_launch(void* const* d_in, const int* in_sizes, int n_in,
                              void* d_out, int out_size)
{
    const float4* pred = (const float4*)d_in[0];
    const float4* targ = (const float4*)d_in[1];
    const float4* x    = (const float4*)d_in[2];
    float* out = (float*)d_out;

    fused_kernel<<<NBLOCKS, THREADS>>>(pred, targ, x, out);
}

// round 4
// speedup vs baseline: 1.1494x; 1.1494x over previous
#include <cuda_runtime.h>

#define NB 32
#define NCH 3
#define THREADS 128
#define B_PER_CHUNK 16
#define CHUNK_ELEMS (512*512)
#define CHUNK_F4   (CHUNK_ELEMS/4)         // 65536 float4 per (n,c) chunk
#define NCHUNKS    (16*3)                  // 48
#define NBLOCKS    (NCHUNKS * B_PER_CHUNK) // 768 (one wave at 6 blocks/SM)
#define STRIDE     (B_PER_CHUNK * THREADS) // 2048

// Global accumulators. Zero-initialized at module load; final_kernel resets
// them after reading, so every (graph-replayed) launch starts from zero.
__device__ double g_sum_d[NCH * NB];
__device__ double g_cnt [NCH * NB];

__device__ __forceinline__ void accum(float2* h, float xc, float pc, float tc, int tid)
{
    int b = (int)(xc * 32.0f);        // inputs uniform [0,1): always valid
    b = min(b, NB - 1);               // guard only
    float2* e = &h[b * THREADS + tid];
    float2 v = *e;                    // LDS.64, conflict-free (lane stride 8B)
    v.x += pc - tc;
    v.y += 1.0f;
    *e = v;                           // STS.64
}

__global__ __launch_bounds__(THREADS, 6)
void hist_kernel(const float4* __restrict__ pred,
                 const float4* __restrict__ targ,
                 const float4* __restrict__ x)
{
    // Per-thread privatized {sum(p-t), count} histogram: h[bin*128 + tid].
    __shared__ float2 h[NB * THREADS];

    const int tid = threadIdx.x;

    #pragma unroll
    for (int b = 0; b < NB; b++)
        h[b * THREADS + tid] = make_float2(0.0f, 0.0f);
    __syncthreads();

    const int chunk = blockIdx.x / B_PER_CHUNK;   // (n*3 + c)
    const int sub   = blockIdx.x % B_PER_CHUNK;
    const int chan  = chunk % NCH;
    const size_t base = (size_t)chunk * CHUNK_F4;

    // 32 float4 slots per thread, processed as 16 iterations of a slot-pair.
    // Software pipeline: next iteration's 6 LDG.128 are issued BEFORE the
    // current iteration's smem-RMW chain, keeping ~3KB/warp in flight.
    int i = sub * THREADS + tid;

    float4 xa = __ldcs(&x   [base + i]);
    float4 pa = __ldcs(&pred[base + i]);
    float4 ta = __ldcs(&targ[base + i]);
    float4 xb = __ldcs(&x   [base + i + STRIDE]);
    float4 pb = __ldcs(&pred[base + i + STRIDE]);
    float4 tb = __ldcs(&targ[base + i + STRIDE]);

    #pragma unroll 1
    for (int k = 0; k < CHUNK_F4 / (2 * STRIDE); k++) {
        float4 cxa = xa, cpa = pa, cta = ta;
        float4 cxb = xb, cpb = pb, ctb = tb;

        i += 2 * STRIDE;
        if (k + 1 < CHUNK_F4 / (2 * STRIDE)) {
            xa = __ldcs(&x   [base + i]);
            pa = __ldcs(&pred[base + i]);
            ta = __ldcs(&targ[base + i]);
            xb = __ldcs(&x   [base + i + STRIDE]);
            pb = __ldcs(&pred[base + i + STRIDE]);
            tb = __ldcs(&targ[base + i + STRIDE]);
        }

        accum(h, cxa.x, cpa.x, cta.x, tid);
        accum(h, cxa.y, cpa.y, cta.y, tid);
        accum(h, cxa.z, cpa.z, cta.z, tid);
        accum(h, cxa.w, cpa.w, cta.w, tid);
        accum(h, cxb.x, cpb.x, ctb.x, tid);
        accum(h, cxb.y, cpb.y, ctb.y, tid);
        accum(h, cxb.z, cpb.z, ctb.z, tid);
        accum(h, cxb.w, cpb.w, ctb.w, tid);
    }
    __syncthreads();

    // Block reduce: 128 threads = 32 bins x 4 quarters of 32 entries.
    const int bin = tid >> 2;
    const int j   = tid & 3;
    const int bi  = bin * THREADS + j * 32;

    float vd = 0.0f, vc = 0.0f;
    #pragma unroll
    for (int k = 0; k < 32; k++) {
        int kk = (k + tid) & 31;
        float2 e = h[bi + kk];
        vd += e.x;
        vc += e.y;
    }

    vd += __shfl_down_sync(0xffffffffu, vd, 1);
    vc += __shfl_down_sync(0xffffffffu, vc, 1);
    vd += __shfl_down_sync(0xffffffffu, vd, 2);
    vc += __shfl_down_sync(0xffffffffu, vc, 2);

    if (j == 0) {
        int g = chan * NB + bin;
        atomicAdd(&g_sum_d[g], (double)vd);
        atomicAdd(&g_cnt [g], (double)vc);
    }
}

__global__ void final_kernel(float* __restrict__ out) {
    // 96 active threads; fp32 math (count is an exact small integer in fp32,
    // sums are O(1e3): fp32 divide error ~1e-7 rel, far under the 1e-3 budget).
    int i = threadIdx.x;
    float d = 0.0f;
    if (i < NCH * NB) {
        float cnt = (float)g_cnt[i];
        float sd  = (float)g_sum_d[i];
        if (cnt > 0.0f) d = fabsf(sd / cnt);
        g_sum_d[i] = 0.0;   // reset for next launch (graph determinism)
        g_cnt [i] = 0.0;
    }
    // warp reduce + cross-warp via smem
    #pragma unroll
    for (int s = 16; s > 0; s >>= 1)
        d += __shfl_down_sync(0xffffffffu, d, s);

    __shared__ float wsum[4];
    if ((i & 31) == 0) wsum[i >> 5] = d;
    __syncthreads();
    if (i == 0) out[0] = (wsum[0] + wsum[1] + wsum[2] + wsum[3]) / 96.0f;
}

extern "C" void kernel_launch(void* const* d_in, const int* in_sizes, int n_in,
                              void* d_out, int out_size)
{
    const float4* pred = (const float4*)d_in[0];
    const float4* targ = (const float4*)d_in[1];
    const float4* x    = (const float4*)d_in[2];
    float* out = (float*)d_out;

    hist_kernel<<<NBLOCKS, THREADS>>>(pred, targ, x);
    final_kernel<<<1, 128>>>(out);
}

// round 6
// speedup vs baseline: 1.1940x; 1.0388x over previous
#include <cuda_runtime.h>

#define NB 32
#define NCH 3
#define THREADS 128
#define B_PER_CHUNK 32
#define CHUNK_ELEMS (512*512)
#define CHUNK_F4   (CHUNK_ELEMS/4)         // 65536 float4 per (n,c) chunk
#define NCHUNKS    (16*3)                  // 48
#define NBLOCKS    (NCHUNKS * B_PER_CHUNK) // 1536 small blocks -> HW load balance
#define STRIDE     (B_PER_CHUNK * THREADS) // 4096

// Global accumulators. Zero-initialized at module load; final_kernel resets
// them after reading, so every (graph-replayed) launch starts from zero.
__device__ double g_sum_d[NCH * NB];
__device__ double g_cnt [NCH * NB];

__device__ __forceinline__ void accum(float2* h, float xc, float pc, float tc, int tid)
{
    int b = (int)(xc * 32.0f);        // inputs uniform [0,1): always valid
    b = min(b, NB - 1);               // guard only
    float2* e = &h[b * THREADS + tid];
    float2 v = *e;                    // LDS.64, conflict-free (lane stride 8B)
    v.x += pc - tc;
    v.y += 1.0f;
    *e = v;                           // STS.64
}

__global__ __launch_bounds__(THREADS, 7)
void hist_kernel(const float4* __restrict__ pred,
                 const float4* __restrict__ targ,
                 const float4* __restrict__ x)
{
    // Per-thread privatized {sum(p-t), count} histogram: h[bin*128 + tid].
    __shared__ float2 h[NB * THREADS];

    const int tid = threadIdx.x;

    #pragma unroll
    for (int b = 0; b < NB; b++)
        h[b * THREADS + tid] = make_float2(0.0f, 0.0f);
    __syncthreads();

    const int chunk = blockIdx.x / B_PER_CHUNK;   // (n*3 + c)
    const int sub   = blockIdx.x % B_PER_CHUNK;
    const int chan  = chunk % NCH;
    const size_t base = (size_t)chunk * CHUNK_F4;

    // 16 float4 slots per thread, processed as 8 iterations of a slot-pair.
    // __restrict__ + unroll lets ptxas front-batch all 12 LDG.128 per iter.
    int i = sub * THREADS + tid;
    #pragma unroll 2
    for (int k = 0; k < CHUNK_F4 / (2 * STRIDE); k++, i += 2 * STRIDE) {
        float4 xa = __ldcs(&x   [base + i]);
        float4 pa = __ldcs(&pred[base + i]);
        float4 ta = __ldcs(&targ[base + i]);
        float4 xb = __ldcs(&x   [base + i + STRIDE]);
        float4 pb = __ldcs(&pred[base + i + STRIDE]);
        float4 tb = __ldcs(&targ[base + i + STRIDE]);

        accum(h, xa.x, pa.x, ta.x, tid);
        accum(h, xa.y, pa.y, ta.y, tid);
        accum(h, xa.z, pa.z, ta.z, tid);
        accum(h, xa.w, pa.w, ta.w, tid);

        accum(h, xb.x, pb.x, tb.x, tid);
        accum(h, xb.y, pb.y, tb.y, tid);
        accum(h, xb.z, pb.z, tb.z, tid);
        accum(h, xb.w, pb.w, tb.w, tid);
    }
    __syncthreads();

    // Block reduce: 128 threads = 32 bins x 4 quarters of 32 entries.
    const int bin = tid >> 2;
    const int j   = tid & 3;
    const int bi  = bin * THREADS + j * 32;

    float vd = 0.0f, vc = 0.0f;
    #pragma unroll
    for (int k = 0; k < 32; k++) {
        int kk = (k + tid) & 31;
        float2 e = h[bi + kk];
        vd += e.x;
        vc += e.y;
    }

    vd += __shfl_down_sync(0xffffffffu, vd, 1);
    vc += __shfl_down_sync(0xffffffffu, vc, 1);
    vd += __shfl_down_sync(0xffffffffu, vd, 2);
    vc += __shfl_down_sync(0xffffffffu, vc, 2);

    if (j == 0) {
        int g = chan * NB + bin;
        atomicAdd(&g_sum_d[g], (double)vd);
        atomicAdd(&g_cnt [g], (double)vc);
    }
}

__global__ void final_kernel(float* __restrict__ out) {
    int i = threadIdx.x;
    float d = 0.0f;
    if (i < NCH * NB) {
        float cnt = (float)g_cnt[i];
        float sd  = (float)g_sum_d[i];
        if (cnt > 0.0f) d = fabsf(sd / cnt);
        g_sum_d[i] = 0.0;   // reset for next launch (graph determinism)
        g_cnt [i] = 0.0;
    }
    #pragma unroll
    for (int s = 16; s > 0; s >>= 1)
        d += __shfl_down_sync(0xffffffffu, d, s);

    __shared__ float wsum[4];
    if ((i & 31) == 0) wsum[i >> 5] = d;
    __syncthreads();
    if (i == 0) out[0] = (wsum[0] + wsum[1] + wsum[2] + wsum[3]) / 96.0f;
}

extern "C" void kernel_launch(void* const* d_in, const int* in_sizes, int n_in,
                              void* d_out, int out_size)
{
    const float4* pred = (const float4*)d_in[0];
    const float4* targ = (const float4*)d_in[1];
    const float4* x    = (const float4*)d_in[2];
    float* out = (float*)d_out;

    hist_kernel<<<NBLOCKS, THREADS>>>(pred, targ, x);
    final_kernel<<<1, 128>>>(out);
}